// round 17
// baseline (speedup 1.0000x reference)
#include <cuda_runtime.h>

// Problem dimensions
static constexpr int NB = 512;   // batch
static constexpr int NT = 512;   // time
static constexpr int NOBS = 64;  // obs dim
static constexpr int NH = 256;   // hidden
static constexpr int NG = 1024;  // 4*H
static constexpr int NLAT = 16;  // latent
static constexpr int NBLK = 128; // persistent grid

// ---------------- scratch (device globals; no allocation allowed) ----------
__device__ float g_xp[(size_t)NT * NB * NH];   // [t*NB + sorted_b][h]
__device__ float g_Wr_ie[NH * NG];             // Wi_e reordered: [k][4j+g]
__device__ float g_Wr_he[NH * NG];             // Wh_e reordered
__device__ float g_Wr_d[NH * NG];              // (Wi_d + Wh_d) reordered
__device__ float g_br_e[NG];                   // b_e reordered
__device__ float g_br_d[NG];                   // b_d reordered
__device__ float g_h[2][NB * NH];              // ping-pong hidden state (sorted order)
__device__ int   g_len[NB];                    // per-row valid length (original order)
__device__ int   g_pos[NB];                    // original b -> sorted position
__device__ int   g_perm[NB];                   // sorted position -> original b
__device__ int   g_lens[NB];                   // lengths in sorted (descending) order
__device__ unsigned g_flag[16][16 * 32];       // per-(group,block) step flags, 128B stride

// ---------------- helpers ---------------------------------------------------
union F2U { unsigned long long u; float f[2]; };

__device__ __forceinline__ void fma2(unsigned long long& d, unsigned long long a,
                                     unsigned long long b) {
    asm("fma.rn.f32x2 %0, %1, %2, %0;" : "+l"(d) : "l"(a), "l"(b));
}

__device__ __forceinline__ unsigned long long dupr(float x) {
    unsigned long long r;
    asm("mov.b64 %0, {%1, %1};" : "=l"(r) : "f"(x));
    return r;
}

__device__ __forceinline__ float fsig(float x) {
    return __fdividef(1.0f, 1.0f + __expf(-x));
}
__device__ __forceinline__ float ftanh(float x) {
    return 1.0f - __fdividef(2.0f, __expf(2.0f * x) + 1.0f);
}

__device__ __forceinline__ void barj(int barid) {
    asm volatile("bar.sync %0, 256;" :: "r"(barid) : "memory");
}

__device__ __forceinline__ void flag_signal(int g, int myslot, unsigned target) {
    asm volatile("st.release.gpu.global.b32 [%0], %1;"
                 :: "l"(&g_flag[g][myslot * 32]), "r"(target) : "memory");
}

__device__ __forceinline__ void flag_wait(int g, unsigned target) {
    const int lane = threadIdx.x & 31;
    if (lane < 16) {
        unsigned cur;
        do {
            asm volatile("ld.acquire.gpu.global.b32 %0, [%1];"
                         : "=r"(cur) : "l"(&g_flag[g][lane * 32]) : "memory");
        } while ((int)(cur - target) < 0);
    }
    __syncwarp();
}

// ---------------- setup: weight reorder + mask lengths + flag reset ----------
__global__ void k_setup(const void* __restrict__ mask,
                        const float* __restrict__ Wi_e, const float* __restrict__ Wh_e,
                        const float* __restrict__ Wi_d, const float* __restrict__ Wh_d,
                        const float* __restrict__ b_e, const float* __restrict__ b_d) {
    const int idx = blockIdx.x * 256 + threadIdx.x;   // grid 1024 x 256 = NH*NG
    {
        int k = idx >> 10, c = idx & 1023;
        int g = c & 3, j = c >> 2;
        int src = k * NG + g * NH + j;
        g_Wr_ie[idx] = Wi_e[src];
        g_Wr_he[idx] = Wh_e[src];
        g_Wr_d[idx]  = Wi_d[src] + Wh_d[src];   // decoder input == hidden -> fold
    }
    if (idx < NG) {
        int g = idx & 3, j = idx >> 2;
        g_br_e[idx] = b_e[g * NH + j];
        g_br_d[idx] = b_d[g * NH + j];
    }
    if (idx < 16 * 16 * 32) ((unsigned*)g_flag)[idx] = 0u;
    if (blockIdx.x < NB) {
        const int b = blockIdx.x, tid = threadIdx.x;
        const bool u8 = (((const int*)mask)[0] != 1);
        int cnt = 0;
        for (int t = tid; t < NT; t += 256)
            cnt += u8 ? (((const unsigned char*)mask)[(size_t)b * NT + t] != 0)
                      : (((const int*)mask)[(size_t)b * NT + t] != 0);
#pragma unroll
        for (int off = 16; off; off >>= 1) cnt += __shfl_xor_sync(0xffffffffu, cnt, off);
        __shared__ int sred[8];
        if ((tid & 31) == 0) sred[tid >> 5] = cnt;
        __syncthreads();
        if (tid == 0) {
            int s = 0;
#pragma unroll
            for (int i = 0; i < 8; i++) s += sred[i];
            g_len[b] = s;
        }
    }
}

// ---------------- sort rows by length (descending), stable -------------------
__global__ void __launch_bounds__(NB) k_sort() {
    __shared__ int slen[NB];
    const int b = threadIdx.x;
    slen[b] = g_len[b];
    __syncthreads();
    const int L = slen[b];
    int rank = 0;
    for (int q = 0; q < NB; q++) {
        int Lq = slen[q];
        rank += (Lq > L) || (Lq == L && q < b);
    }
    g_pos[b] = rank;
    g_perm[rank] = b;
    g_lens[rank] = L;
}

// ---------------- K1: input projection  xp = leaky(x @ Wip + bip) -----------
__global__ void __launch_bounds__(256) k_inproj(const float* __restrict__ x,
                                                const float* __restrict__ Wip,
                                                const float* __restrict__ bip) {
    __shared__ __align__(16) float sA[16][64];
    __shared__ __align__(16) float sB[16][64];
    const int tid = threadIdx.x;
    const int r0 = blockIdx.x * 64, c0 = blockIdx.y * 64;
    const int tx = tid & 15, ty = tid >> 4;
    const int am = tid >> 2, ak = (tid & 3) * 4;
    const int bk = tid >> 4, bc = (tid & 15) * 4;
    float acc[4][4] = {};
    for (int k0 = 0; k0 < NOBS; k0 += 16) {
        int r = r0 + am;
        int t = r >> 9;
        int b = r & (NB - 1);
        float4 av = *reinterpret_cast<const float4*>(&x[((size_t)b * NT + t) * NOBS + k0 + ak]);
        sA[ak + 0][am] = av.x; sA[ak + 1][am] = av.y;
        sA[ak + 2][am] = av.z; sA[ak + 3][am] = av.w;
        float4 bv = *reinterpret_cast<const float4*>(&Wip[(size_t)(k0 + bk) * NH + c0 + bc]);
        *reinterpret_cast<float4*>(&sB[bk][bc]) = bv;
        __syncthreads();
#pragma unroll
        for (int kk = 0; kk < 16; kk++) {
            float4 a4 = *reinterpret_cast<const float4*>(&sA[kk][ty * 4]);
            float4 b4 = *reinterpret_cast<const float4*>(&sB[kk][tx * 4]);
            float ar[4] = {a4.x, a4.y, a4.z, a4.w};
            float br[4] = {b4.x, b4.y, b4.z, b4.w};
#pragma unroll
            for (int i = 0; i < 4; i++)
#pragma unroll
                for (int jj = 0; jj < 4; jj++)
                    acc[i][jj] += ar[i] * br[jj];
        }
        __syncthreads();
    }
#pragma unroll
    for (int i = 0; i < 4; i++) {
        int r = r0 + ty * 4 + i;
        int t = r >> 9;
        int b = r & (NB - 1);
        size_t wr = (size_t)t * NB + g_pos[b];
        float4 v;
        float z0 = acc[i][0] + bip[c0 + tx * 4 + 0];
        float z1 = acc[i][1] + bip[c0 + tx * 4 + 1];
        float z2 = acc[i][2] + bip[c0 + tx * 4 + 2];
        float z3 = acc[i][3] + bip[c0 + tx * 4 + 3];
        v.x = z0 > 0.0f ? z0 : 0.01f * z0;
        v.y = z1 > 0.0f ? z1 : 0.01f * z1;
        v.z = z2 > 0.0f ? z2 : 0.01f * z2;
        v.w = z3 > 0.0f ? z3 : 0.01f * z3;
        *reinterpret_cast<float4*>(&g_xp[wr * NH + c0 + tx * 4]) = v;
    }
}

// ---------------- encoder scan: fused x-GEMM, early exit, symmetric epilogue -
// Each warp-half publishes partials for the 2 rows it does NOT handle and runs
// gates for its own 2 rows (MUFU chain halved). x-stage shares the epilogue
// barrier (sAj free after the sR barrier) -> 4 named barriers per step.
__global__ void __launch_bounds__(512, 1) k_escan() {
    extern __shared__ float sm[];
    float* sWh = sm;                       // [256 k][64]  Wh_e tile   64 KB
    float* sWi = sWh + NH * 64;            // [256 k][64]  Wi_e tile   64 KB
    float* sA  = sWi + NH * 64;            // 2 x [256 k][32 rows]     64 KB
    float* sR  = sA + 2 * NH * 32;         // 2 x [16][128] partials   16 KB

    const int tid  = threadIdx.x;
    const int jid  = tid >> 8;
    const int jtid = tid & 255;
    const int barid = 1 + jid;
    const int by = blockIdx.x >> 3;
    const int g  = (blockIdx.x & 7) + jid * 8;
    const int b0 = g * 32;
    const int c0 = by * 64;
    const int sub = jtid & 127;
    const int kb  = (jtid >> 7) * 128;
    const int tx = sub & 15, ty = sub >> 4;
    const int j  = (c0 >> 2) + tx;
    const int sr  = jtid & 31;
    const int sk0 = (jtid >> 5) * 32;
    float* sAj = sA + jid * NH * 32;
    float* sRj = sR + jid * 16 * 128;
    const bool lower = (jtid < 128);
    const int ro = lower ? 0 : 2;          // epilogue row base for this half
    const int TG = g_lens[b0];             // group max length (descending sort)

    for (int q = tid; q < NH * 16; q += 512) {
        int k = q >> 4, cc = (q & 15) * 4;
        *reinterpret_cast<float4*>(&sWh[k * 64 + cc]) =
            *reinterpret_cast<const float4*>(&g_Wr_he[(size_t)k * NG + c0 + cc]);
        *reinterpret_cast<float4*>(&sWi[k * 64 + cc]) =
            *reinterpret_cast<const float4*>(&g_Wr_ie[(size_t)k * NG + c0 + cc]);
    }
    const float4 bv = *reinterpret_cast<const float4*>(&g_br_e[c0 + tx * 4]);

    float rc2[2], rh2[2];
    int rlen2[2];
#pragma unroll
    for (int i2 = 0; i2 < 2; i2++) {
        const int b = b0 + ty * 4 + ro + i2;
        rc2[i2] = 0.0f; rh2[i2] = 0.0f; rlen2[i2] = g_lens[b];
        g_h[0][b * NH + j] = 0.0f;
    }
    __syncthreads();
    if (jtid == 0) flag_signal(g, by, 1u);

    F2U acc[4][2];

    // ---- prologue: zx for step 0 ----
    {
        float4 tmp[8];
#pragma unroll
        for (int i = 0; i < 8; i++)
            tmp[i] = *reinterpret_cast<const float4*>(
                &g_xp[(size_t)(b0 + sr) * NH + sk0 + 4 * i]);
#pragma unroll
        for (int i = 0; i < 8; i++) {
            sAj[(sk0 + 4 * i + 0) * 32 + sr] = tmp[i].x;
            sAj[(sk0 + 4 * i + 1) * 32 + sr] = tmp[i].y;
            sAj[(sk0 + 4 * i + 2) * 32 + sr] = tmp[i].z;
            sAj[(sk0 + 4 * i + 3) * 32 + sr] = tmp[i].w;
        }
    }
    barj(barid);
#pragma unroll
    for (int i = 0; i < 4; i++) {
        if (kb == 0) {
            acc[i][0].f[0] = bv.x; acc[i][0].f[1] = bv.y;
            acc[i][1].f[0] = bv.z; acc[i][1].f[1] = bv.w;
        } else { acc[i][0].u = 0ull; acc[i][1].u = 0ull; }
    }
    {
        float4 a_cur = *reinterpret_cast<const float4*>(&sAj[kb * 32 + ty * 4]);
        ulonglong2 b_cur = *reinterpret_cast<const ulonglong2*>(&sWi[kb * 64 + tx * 4]);
#pragma unroll 8
        for (int k = kb; k < kb + 127; k++) {
            float4 a_nxt = *reinterpret_cast<const float4*>(&sAj[(k + 1) * 32 + ty * 4]);
            ulonglong2 b_nxt = *reinterpret_cast<const ulonglong2*>(&sWi[(k + 1) * 64 + tx * 4]);
            unsigned long long a0 = dupr(a_cur.x), a1 = dupr(a_cur.y);
            unsigned long long a2 = dupr(a_cur.z), a3 = dupr(a_cur.w);
            fma2(acc[0][0].u, a0, b_cur.x); fma2(acc[0][1].u, a0, b_cur.y);
            fma2(acc[1][0].u, a1, b_cur.x); fma2(acc[1][1].u, a1, b_cur.y);
            fma2(acc[2][0].u, a2, b_cur.x); fma2(acc[2][1].u, a2, b_cur.y);
            fma2(acc[3][0].u, a3, b_cur.x); fma2(acc[3][1].u, a3, b_cur.y);
            a_cur = a_nxt; b_cur = b_nxt;
        }
        unsigned long long a0 = dupr(a_cur.x), a1 = dupr(a_cur.y);
        unsigned long long a2 = dupr(a_cur.z), a3 = dupr(a_cur.w);
        fma2(acc[0][0].u, a0, b_cur.x); fma2(acc[0][1].u, a0, b_cur.y);
        fma2(acc[1][0].u, a1, b_cur.x); fma2(acc[1][1].u, a1, b_cur.y);
        fma2(acc[2][0].u, a2, b_cur.x); fma2(acc[2][1].u, a2, b_cur.y);
        fma2(acc[3][0].u, a3, b_cur.x); fma2(acc[3][1].u, a3, b_cur.y);
    }
    barj(barid);
    flag_wait(g, 1u);

    for (int t = 0; t < TG; t++) {
        const float* __restrict__ h_in = g_h[t & 1];
        float* __restrict__ h_out = g_h[(t & 1) ^ 1];

        // ---- stage h[t] tile ----
        {
            float4 tmp[8];
#pragma unroll
            for (int i = 0; i < 8; i++)
                tmp[i] = *reinterpret_cast<const float4*>(
                    &h_in[(size_t)(b0 + sr) * NH + sk0 + 4 * i]);
#pragma unroll
            for (int i = 0; i < 8; i++) {
                sAj[(sk0 + 4 * i + 0) * 32 + sr] = tmp[i].x;
                sAj[(sk0 + 4 * i + 1) * 32 + sr] = tmp[i].y;
                sAj[(sk0 + 4 * i + 2) * 32 + sr] = tmp[i].z;
                sAj[(sk0 + 4 * i + 3) * 32 + sr] = tmp[i].w;
            }
        }
        barj(barid);

        // ---- h-GEMM accumulating onto zx partials ----
        {
            float4 a_cur = *reinterpret_cast<const float4*>(&sAj[kb * 32 + ty * 4]);
            ulonglong2 b_cur = *reinterpret_cast<const ulonglong2*>(&sWh[kb * 64 + tx * 4]);
#pragma unroll 8
            for (int k = kb; k < kb + 127; k++) {
                float4 a_nxt = *reinterpret_cast<const float4*>(&sAj[(k + 1) * 32 + ty * 4]);
                ulonglong2 b_nxt = *reinterpret_cast<const ulonglong2*>(&sWh[(k + 1) * 64 + tx * 4]);
                unsigned long long a0 = dupr(a_cur.x), a1 = dupr(a_cur.y);
                unsigned long long a2 = dupr(a_cur.z), a3 = dupr(a_cur.w);
                fma2(acc[0][0].u, a0, b_cur.x); fma2(acc[0][1].u, a0, b_cur.y);
                fma2(acc[1][0].u, a1, b_cur.x); fma2(acc[1][1].u, a1, b_cur.y);
                fma2(acc[2][0].u, a2, b_cur.x); fma2(acc[2][1].u, a2, b_cur.y);
                fma2(acc[3][0].u, a3, b_cur.x); fma2(acc[3][1].u, a3, b_cur.y);
                a_cur = a_nxt; b_cur = b_nxt;
            }
            unsigned long long a0 = dupr(a_cur.x), a1 = dupr(a_cur.y);
            unsigned long long a2 = dupr(a_cur.z), a3 = dupr(a_cur.w);
            fma2(acc[0][0].u, a0, b_cur.x); fma2(acc[0][1].u, a0, b_cur.y);
            fma2(acc[1][0].u, a1, b_cur.x); fma2(acc[1][1].u, a1, b_cur.y);
            fma2(acc[2][0].u, a2, b_cur.x); fma2(acc[2][1].u, a2, b_cur.y);
            fma2(acc[3][0].u, a3, b_cur.x); fma2(acc[3][1].u, a3, b_cur.y);
        }

        // ---- publish partials for the 2 rows this half does NOT handle ----
        if (lower) {
#pragma unroll
            for (int i = 2; i < 4; i++) {
                sRj[((i - 2) * 4 + 0) * 128 + sub] = acc[i][0].f[0];
                sRj[((i - 2) * 4 + 1) * 128 + sub] = acc[i][0].f[1];
                sRj[((i - 2) * 4 + 2) * 128 + sub] = acc[i][1].f[0];
                sRj[((i - 2) * 4 + 3) * 128 + sub] = acc[i][1].f[1];
            }
        } else {
#pragma unroll
            for (int i = 0; i < 2; i++) {
                sRj[(8 + i * 4 + 0) * 128 + sub] = acc[i][0].f[0];
                sRj[(8 + i * 4 + 1) * 128 + sub] = acc[i][0].f[1];
                sRj[(8 + i * 4 + 2) * 128 + sub] = acc[i][1].f[0];
                sRj[(8 + i * 4 + 3) * 128 + sub] = acc[i][1].f[1];
            }
        }
        barj(barid);

        // ---- symmetric epilogue: 2 rows per half ----
#pragma unroll
        for (int i2 = 0; i2 < 2; i2++) {
            const int i = ro + i2;
            const int b = b0 + ty * 4 + i;
            const int base = lower ? (8 + i * 4) : ((i - 2) * 4);
            float zi = acc[i][0].f[0] + sRj[(base + 0) * 128 + sub];
            float zf = acc[i][0].f[1] + sRj[(base + 1) * 128 + sub];
            float zg = acc[i][1].f[0] + sRj[(base + 2) * 128 + sub];
            float zo = acc[i][1].f[1] + sRj[(base + 3) * 128 + sub];
            float ig = fsig(zi), fg = fsig(zf), gg = ftanh(zg), og = fsig(zo);
            float nc = fg * rc2[i2] + ig * gg;
            float nh = og * ftanh(nc);
            bool m = (t < rlen2[i2]);
            rc2[i2] = m ? nc : rc2[i2];
            rh2[i2] = m ? nh : rh2[i2];
            h_out[b * NH + j] = rh2[i2];
        }

        if (t + 1 < TG) {
            // ---- stage xp[t+1] (sAj free since the sR barrier) ----
            {
                float4 tmp[8];
#pragma unroll
                for (int i = 0; i < 8; i++)
                    tmp[i] = *reinterpret_cast<const float4*>(
                        &g_xp[((size_t)(t + 1) * NB + b0 + sr) * NH + sk0 + 4 * i]);
#pragma unroll
                for (int i = 0; i < 8; i++) {
                    sAj[(sk0 + 4 * i + 0) * 32 + sr] = tmp[i].x;
                    sAj[(sk0 + 4 * i + 1) * 32 + sr] = tmp[i].y;
                    sAj[(sk0 + 4 * i + 2) * 32 + sr] = tmp[i].z;
                    sAj[(sk0 + 4 * i + 3) * 32 + sr] = tmp[i].w;
                }
            }
            barj(barid);                   // h_out done (program order) + x staged
            if (jtid == 0) flag_signal(g, by, (unsigned)(t + 2));

            // ---- x-GEMM in the wait window ----
#pragma unroll
            for (int i = 0; i < 4; i++) {
                if (kb == 0) {
                    acc[i][0].f[0] = bv.x; acc[i][0].f[1] = bv.y;
                    acc[i][1].f[0] = bv.z; acc[i][1].f[1] = bv.w;
                } else { acc[i][0].u = 0ull; acc[i][1].u = 0ull; }
            }
            {
                float4 a_cur = *reinterpret_cast<const float4*>(&sAj[kb * 32 + ty * 4]);
                ulonglong2 b_cur = *reinterpret_cast<const ulonglong2*>(&sWi[kb * 64 + tx * 4]);
#pragma unroll 8
                for (int k = kb; k < kb + 127; k++) {
                    float4 a_nxt = *reinterpret_cast<const float4*>(&sAj[(k + 1) * 32 + ty * 4]);
                    ulonglong2 b_nxt = *reinterpret_cast<const ulonglong2*>(&sWi[(k + 1) * 64 + tx * 4]);
                    unsigned long long a0 = dupr(a_cur.x), a1 = dupr(a_cur.y);
                    unsigned long long a2 = dupr(a_cur.z), a3 = dupr(a_cur.w);
                    fma2(acc[0][0].u, a0, b_cur.x); fma2(acc[0][1].u, a0, b_cur.y);
                    fma2(acc[1][0].u, a1, b_cur.x); fma2(acc[1][1].u, a1, b_cur.y);
                    fma2(acc[2][0].u, a2, b_cur.x); fma2(acc[2][1].u, a2, b_cur.y);
                    fma2(acc[3][0].u, a3, b_cur.x); fma2(acc[3][1].u, a3, b_cur.y);
                    a_cur = a_nxt; b_cur = b_nxt;
                }
                unsigned long long a0 = dupr(a_cur.x), a1 = dupr(a_cur.y);
                unsigned long long a2 = dupr(a_cur.z), a3 = dupr(a_cur.w);
                fma2(acc[0][0].u, a0, b_cur.x); fma2(acc[0][1].u, a0, b_cur.y);
                fma2(acc[1][0].u, a1, b_cur.x); fma2(acc[1][1].u, a1, b_cur.y);
                fma2(acc[2][0].u, a2, b_cur.x); fma2(acc[2][1].u, a2, b_cur.y);
                fma2(acc[3][0].u, a3, b_cur.x); fma2(acc[3][1].u, a3, b_cur.y);
            }
            barj(barid);                   // x-GEMM reads done before next stage
            flag_wait(g, (unsigned)(t + 2));
        }
    }

    // final h must end in buffer 0 for k_latctx
    if (TG & 1) {
#pragma unroll
        for (int i2 = 0; i2 < 2; i2++)
            g_h[0][(b0 + ty * 4 + ro + i2) * NH + j] = rh2[i2];
    }
}

// ---------------- decoder scan: symmetric epilogue + windowed pred -----------
__global__ void __launch_bounds__(512, 1) k_dscan(unsigned ebase,
                                                  const float* __restrict__ Wop,
                                                  const float* __restrict__ bop,
                                                  float* __restrict__ out) {
    extern __shared__ float sm[];
    float* sW  = sm;                       // [256 k][64]             64 KB
    float* sA  = sm + NH * 64;             // 2 x [256 k][32 rows]    64 KB
    float* sR  = sA + 2 * NH * 32;         // 2 x [16][128] partials  16 KB
    float* sRp = sR + 2 * 16 * 128;        // 2 x [128] pred partials  1 KB
    float* sP  = sRp + 2 * 128;            // [256 k][4] Wop tile      4 KB

    const int tid  = threadIdx.x;
    const int jid  = tid >> 8;
    const int jtid = tid & 255;
    const int barid = 1 + jid;
    const int by = blockIdx.x >> 3;
    const int g  = (blockIdx.x & 7) + jid * 8;
    const int b0 = g * 32;
    const int c0 = by * 64;
    const int sub = jtid & 127;
    const int kb  = (jtid >> 7) * 128;
    const int tx = sub & 15, ty = sub >> 4;
    const int j  = (c0 >> 2) + tx;
    const int pr = sub >> 2, pc = sub & 3;
    const int sr  = jtid & 31;
    const int sk0 = (jtid >> 5) * 32;
    float* sAj  = sA + jid * NH * 32;
    float* sRj  = sR + jid * 16 * 128;
    float* sRpj = sRp + jid * 128;
    const bool lower = (jtid < 128);
    const int ro = lower ? 0 : 2;
    const int ob = g_perm[b0 + pr];        // original row for recon stores

    for (int q = tid; q < NH * 16; q += 512) {
        int k = q >> 4, cc = (q & 15) * 4;
        *reinterpret_cast<float4*>(&sW[k * 64 + cc]) =
            *reinterpret_cast<const float4*>(&g_Wr_d[(size_t)k * NG + c0 + cc]);
    }
    for (int q = tid; q < NH * 4; q += 512)
        sP[q] = Wop[(q >> 2) * NOBS + by * 4 + (q & 3)];
    const float4 bv = *reinterpret_cast<const float4*>(&g_br_d[c0 + tx * 4]);
    const float bopv = bop[by * 4 + pc];

    float rc2[2], rh2[2];
#pragma unroll
    for (int i2 = 0; i2 < 2; i2++) {
        const int b = b0 + ty * 4 + ro + i2;
        float v = g_h[0][b * NH + j];
        rc2[i2] = v; rh2[i2] = v;
    }
    __syncthreads();

    for (int t = 0; t <= NT; t++) {
        const float* __restrict__ h_in = g_h[t & 1];
        float* __restrict__ h_out = g_h[(t & 1) ^ 1];

        // ---- stage h[t] tile ----
        {
            float4 tmp[8];
#pragma unroll
            for (int i = 0; i < 8; i++)
                tmp[i] = *reinterpret_cast<const float4*>(
                    &h_in[(size_t)(b0 + sr) * NH + sk0 + 4 * i]);
#pragma unroll
            for (int i = 0; i < 8; i++) {
                sAj[(sk0 + 4 * i + 0) * 32 + sr] = tmp[i].x;
                sAj[(sk0 + 4 * i + 1) * 32 + sr] = tmp[i].y;
                sAj[(sk0 + 4 * i + 2) * 32 + sr] = tmp[i].z;
                sAj[(sk0 + 4 * i + 3) * 32 + sr] = tmp[i].w;
            }
        }
        barj(barid);

        if (t < NT) {
            // ---- gates GEMM (no pred loads) ----
            F2U acc[4][2];
#pragma unroll
            for (int i = 0; i < 4; i++) { acc[i][0].u = 0ull; acc[i][1].u = 0ull; }

            float4 a_cur = *reinterpret_cast<const float4*>(&sAj[kb * 32 + ty * 4]);
            ulonglong2 b_cur = *reinterpret_cast<const ulonglong2*>(&sW[kb * 64 + tx * 4]);
#pragma unroll 8
            for (int k = kb; k < kb + 127; k++) {
                float4 a_nxt = *reinterpret_cast<const float4*>(&sAj[(k + 1) * 32 + ty * 4]);
                ulonglong2 b_nxt = *reinterpret_cast<const ulonglong2*>(&sW[(k + 1) * 64 + tx * 4]);
                unsigned long long a0 = dupr(a_cur.x), a1 = dupr(a_cur.y);
                unsigned long long a2 = dupr(a_cur.z), a3 = dupr(a_cur.w);
                fma2(acc[0][0].u, a0, b_cur.x); fma2(acc[0][1].u, a0, b_cur.y);
                fma2(acc[1][0].u, a1, b_cur.x); fma2(acc[1][1].u, a1, b_cur.y);
                fma2(acc[2][0].u, a2, b_cur.x); fma2(acc[2][1].u, a2, b_cur.y);
                fma2(acc[3][0].u, a3, b_cur.x); fma2(acc[3][1].u, a3, b_cur.y);
                a_cur = a_nxt; b_cur = b_nxt;
            }
            {
                unsigned long long a0 = dupr(a_cur.x), a1 = dupr(a_cur.y);
                unsigned long long a2 = dupr(a_cur.z), a3 = dupr(a_cur.w);
                fma2(acc[0][0].u, a0, b_cur.x); fma2(acc[0][1].u, a0, b_cur.y);
                fma2(acc[1][0].u, a1, b_cur.x); fma2(acc[1][1].u, a1, b_cur.y);
                fma2(acc[2][0].u, a2, b_cur.x); fma2(acc[2][1].u, a2, b_cur.y);
                fma2(acc[3][0].u, a3, b_cur.x); fma2(acc[3][1].u, a3, b_cur.y);
            }

            // ---- publish partials for the 2 rows this half does NOT handle --
            if (lower) {
#pragma unroll
                for (int i = 2; i < 4; i++) {
                    sRj[((i - 2) * 4 + 0) * 128 + sub] = acc[i][0].f[0];
                    sRj[((i - 2) * 4 + 1) * 128 + sub] = acc[i][0].f[1];
                    sRj[((i - 2) * 4 + 2) * 128 + sub] = acc[i][1].f[0];
                    sRj[((i - 2) * 4 + 3) * 128 + sub] = acc[i][1].f[1];
                }
            } else {
#pragma unroll
                for (int i = 0; i < 2; i++) {
                    sRj[(8 + i * 4 + 0) * 128 + sub] = acc[i][0].f[0];
                    sRj[(8 + i * 4 + 1) * 128 + sub] = acc[i][0].f[1];
                    sRj[(8 + i * 4 + 2) * 128 + sub] = acc[i][1].f[0];
                    sRj[(8 + i * 4 + 3) * 128 + sub] = acc[i][1].f[1];
                }
            }
            barj(barid);

            // ---- symmetric epilogue: 2 rows per half ----
#pragma unroll
            for (int i2 = 0; i2 < 2; i2++) {
                const int i = ro + i2;
                const int b = b0 + ty * 4 + i;
                const int base = lower ? (8 + i * 4) : ((i - 2) * 4);
                float zi = acc[i][0].f[0] + sRj[(base + 0) * 128 + sub] + bv.x;
                float zf = acc[i][0].f[1] + sRj[(base + 1) * 128 + sub] + bv.y;
                float zg = acc[i][1].f[0] + sRj[(base + 2) * 128 + sub] + bv.z;
                float zo = acc[i][1].f[1] + sRj[(base + 3) * 128 + sub] + bv.w;
                float ig = fsig(zi), fg = fsig(zf), gg = ftanh(zg), og = fsig(zo);
                float nc = fg * rc2[i2] + ig * gg;
                float nh = og * ftanh(nc);
                rc2[i2] = nc; rh2[i2] = nh;
                h_out[b * NH + j] = nh;
            }
            barj(barid);
            if (jtid == 0) flag_signal(g, by, ebase + (unsigned)(t + 1));
        }

        // ---- pred GEMM from still-staged sAj = h[t] -> recon[t-1] ----
        if (t >= 1) {
            float accp = 0.0f;
            float p_cur = sAj[kb * 32 + pr], w_cur = sP[kb * 4 + pc];
#pragma unroll 8
            for (int k = kb; k < kb + 127; k++) {
                float p_nxt = sAj[(k + 1) * 32 + pr];
                float w_nxt = sP[(k + 1) * 4 + pc];
                accp = fmaf(p_cur, w_cur, accp);
                p_cur = p_nxt; w_cur = w_nxt;
            }
            accp = fmaf(p_cur, w_cur, accp);
            if (!lower) sRpj[sub] = accp;
            barj(barid);
            if (lower)
                out[((size_t)ob * NT + (t - 1)) * NOBS + by * 4 + pc] =
                    accp + sRpj[sub] + bopv;
        }

        if (t < NT) flag_wait(g, ebase + (unsigned)(t + 1));
    }
}

// ---------------- latent + context (fused; de-permute latent store) ----------
__global__ void k_latctx(const float* __restrict__ Wlp, const float* __restrict__ blp,
                         const float* __restrict__ Wle, const float* __restrict__ ble,
                         float* __restrict__ out) {
    __shared__ float slat[NLAT];
    const int b = blockIdx.x, tid = threadIdx.x;
    const int l = tid >> 4, sub = tid & 15;
    const float* h = g_h[0];
    float s = 0.0f;
    for (int k = sub; k < NH; k += 16) s += h[b * NH + k] * Wlp[k * NLAT + l];
#pragma unroll
    for (int off = 8; off; off >>= 1) s += __shfl_xor_sync(0xffffffffu, s, off);
    if (sub == 0) {
        float v = s + blp[l];
        slat[l] = v;
        out[(size_t)NB * NT * NOBS + (size_t)g_perm[b] * NLAT + l] = v;
    }
    __syncthreads();
    float s2 = ble[tid];
#pragma unroll
    for (int l2 = 0; l2 < NLAT; l2++) s2 += slat[l2] * Wle[l2 * NH + tid];
    g_h[0][b * NH + tid] = s2 > 0.0f ? s2 : 0.01f * s2;
}

// ---------------- driver -----------------------------------------------------
extern "C" void kernel_launch(void* const* d_in, const int* in_sizes, int n_in,
                              void* d_out, int out_size) {
    (void)in_sizes; (void)n_in; (void)out_size;
    const float* x    = (const float*)d_in[0];
    const void*  mask = d_in[1];
    const float* Wip  = (const float*)d_in[2];
    const float* bip  = (const float*)d_in[3];
    const float* Wi_e = (const float*)d_in[4];
    const float* Wh_e = (const float*)d_in[5];
    const float* b_e  = (const float*)d_in[6];
    const float* Wlp  = (const float*)d_in[7];
    const float* blp  = (const float*)d_in[8];
    const float* Wle  = (const float*)d_in[9];
    const float* ble  = (const float*)d_in[10];
    const float* Wi_d = (const float*)d_in[11];
    const float* Wh_d = (const float*)d_in[12];
    const float* b_d  = (const float*)d_in[13];
    const float* Wop  = (const float*)d_in[14];
    const float* bop  = (const float*)d_in[15];
    float* out = (float*)d_out;

    const size_t smem_e = (size_t)(NH * 64 * 2 + 2 * NH * 32 + 2 * 16 * 128) * sizeof(float);
    const size_t smem_d = (size_t)(NH * 64 + 2 * NH * 32 + 2 * 16 * 128 + 2 * 128 + NH * 4)
                          * sizeof(float);
    cudaFuncSetAttribute(k_escan, cudaFuncAttributeMaxDynamicSharedMemorySize, (int)smem_e);
    cudaFuncSetAttribute(k_dscan, cudaFuncAttributeMaxDynamicSharedMemorySize, (int)smem_d);

    // 6 graph nodes total
    k_setup<<<1024, 256>>>(mask, Wi_e, Wh_e, Wi_d, Wh_d, b_e, b_d);
    k_sort<<<1, NB>>>();
    k_inproj<<<dim3(NB * NT / 64, NH / 64), 256>>>(x, Wip, bip);
    k_escan<<<NBLK, 512, smem_e>>>();
    k_latctx<<<NB, 256>>>(Wlp, blp, Wle, ble, out);
    k_dscan<<<NBLK, 512, smem_d>>>(513u, Wop, bop, out);
}